// round 17
// baseline (speedup 1.0000x reference)
#include <cuda_runtime.h>
#include <cuda_fp8.h>
#include <cstdint>

#define BB 64
#define SS 576
#define DD 768
#define CC 200
#define NP2 224            // padded class dim (28 frags, 4 n-warps x 7)
#define MT 64              // s-rows per CTA (576 = 9*64, exact)
#define KC 64              // K chunk (2 x k32 steps per barrier)
#define NK 12              // 768/64
#define NSB 3              // B stages
#define THREADS 512

#define WSCALE 32.0f
#define WINV   0.03125f

#define B8_STRIDE 80       // bytes per B row (64 data + 16 pad): LDSM conflict-free

#define SZ_BSTG  (NP2 * B8_STRIDE)                      // 17920 per stage
#define OFF_B8   0
#define OFF_RS   (NSB * SZ_BSTG)                        // 53760
#define OFF_WS   (OFF_RS + MT * 4)                      // 54016
#define SMEM_TOTAL (OFF_WS + 4 * NP2 * 4)               // 57600 -> occ 2 (512thr)

// e4m3 copy of attn_w * 32, zero-padded to NP2 rows (static scratch, no allocs)
__device__ uint8_t g_w8[NP2 * DD];

__device__ __forceinline__ uint32_t smem_u32(const void* p) {
    uint32_t a;
    asm("{ .reg .u64 t; cvta.to.shared.u64 t, %1; cvt.u32.u64 %0, t; }" : "=r"(a) : "l"(p));
    return a;
}
__device__ __forceinline__ void cp_async16(uint32_t dst, const void* src) {
    asm volatile("{ .reg .u64 g; cvta.to.global.u64 g, %1; cp.async.cg.shared.global [%0], [g], 16; }"
                 :: "r"(dst), "l"(src) : "memory");
}
#define CP_COMMIT() asm volatile("cp.async.commit_group;" ::: "memory")
#define CP_WAIT1()  asm volatile("cp.async.wait_group 1;" ::: "memory")

#define LDSM4(r0, r1, r2, r3, addr)                                           \
    asm volatile("ldmatrix.sync.aligned.m8n8.x4.shared.b16 {%0,%1,%2,%3}, [%4];" \
        : "=r"(r0), "=r"(r1), "=r"(r2), "=r"(r3) : "r"(addr))
#define LDSM2(r0, r1, addr)                                                   \
    asm volatile("ldmatrix.sync.aligned.m8n8.x2.shared.b16 {%0,%1}, [%2];"    \
        : "=r"(r0), "=r"(r1) : "r"(addr))

#define MMA8(c, a0, a1, a2, a3, b0, b1)                                       \
    asm volatile("mma.sync.aligned.m16n8k32.row.col.f32.e4m3.e4m3.f32 "       \
        "{%0,%1,%2,%3},{%4,%5,%6,%7},{%8,%9},{%0,%1,%2,%3};"                  \
        : "+f"((c)[0]), "+f"((c)[1]), "+f"((c)[2]), "+f"((c)[3])              \
        : "r"(a0), "r"(a1), "r"(a2), "r"(a3), "r"(b0), "r"(b1))

__device__ __forceinline__ float sigf(float x) { return 1.f / (1.f + __expf(-x)); }

// pack 4 floats -> 4 e4m3 bytes, k ascending low->high byte.
__device__ __forceinline__ uint32_t pack4_e4m3(float4 v) {
    uint16_t lo, hi;
    asm("cvt.rn.satfinite.e4m3x2.f32 %0, %2, %1;" : "=h"(lo) : "f"(v.x), "f"(v.y));
    asm("cvt.rn.satfinite.e4m3x2.f32 %0, %2, %1;" : "=h"(hi) : "f"(v.z), "f"(v.w));
    return (uint32_t)lo | ((uint32_t)hi << 16);
}

// ---------------------------------------------------------------------------
// prep kernel: blocks [0,84): attn_w * 32 -> g_w8 (e4m3, zero-padded rows)
//              blocks [84,1684): global_scores = class_token @ gc_w^T + gc_b
// ---------------------------------------------------------------------------
__global__ void prep_kernel(const float* __restrict__ aw,
                            const float* __restrict__ ct,
                            const float* __restrict__ gcw,
                            const float* __restrict__ gcb,
                            float* __restrict__ out) {
    int bid = blockIdx.x;
    if (bid < 84) {
        int base = bid * 2048 + threadIdx.x * 8;   // 84*2048 = NP2*DD
        #pragma unroll
        for (int i = 0; i < 8; i += 4) {
            int idx = base + i;
            int c = idx / DD;
            float s = (c < CC) ? WSCALE : 0.f;
            float4 v = make_float4(aw[idx] * s, aw[idx + 1] * s,
                                   aw[idx + 2] * s, aw[idx + 3] * s);
            // for c >= CC, aw[idx] reads out of range of valid rows only if
            // idx >= CC*DD; those rows use s=0 but still index aw -> clamp:
            if (c >= CC) v = make_float4(0.f, 0.f, 0.f, 0.f);
            *reinterpret_cast<uint32_t*>(g_w8 + idx) = pack4_e4m3(v);
        }
    } else {
        int W = (bid - 84) * 8 + (threadIdx.x >> 5);   // 0..12799
        int lane = threadIdx.x & 31;
        int b = W & 63;
        int c = W >> 6;                                // 0..199
        const float* x = ct + (size_t)b * DD;
        const float* w = gcw + (size_t)c * DD;
        float acc = 0.f;
        #pragma unroll 4
        for (int d = lane; d < DD; d += 32) acc += x[d] * w[d];
        #pragma unroll
        for (int m = 16; m; m >>= 1) acc += __shfl_xor_sync(0xffffffffu, acc, m);
        if (lane == 0) out[b * CC + c] = acc + gcb[c];
    }
}

// ---------------------------------------------------------------------------
// attn kernel: logits = patch @ attn_w^T via fp8 e4m3 mma.sync m16n8k32.
// 512 threads, 16 warps as 4(m) x 4(n); warp tile 16 x 56 (7 nfrags, f32 acc).
// A: per-warp direct LDG.128 fragment layout -> register e4m3 pack (1 it ahead).
// B: cp.async fp8 ring (3 stages), batched ldmatrix; ONE barrier per KC=64.
// Epilogue: per-wm wsum slices (plain STS, no atomics).
// ---------------------------------------------------------------------------
__global__ void __launch_bounds__(THREADS, 2)
attn_kernel(const float* __restrict__ patch,
            const float* __restrict__ attn_b,
            const float* __restrict__ lam,
            float* __restrict__ out) {
    extern __shared__ __align__(16) char smem[];
    float* rs   = (float*)(smem + OFF_RS);
    float* wsum = (float*)(smem + OFF_WS);          // [4][NP2]
    const uint32_t sb = smem_u32(smem);

    const int tid  = threadIdx.x;
    const int lane = tid & 31;
    const int warp = tid >> 5;
    const int wm   = warp >> 2;          // 0..3
    const int wn   = warp & 3;           // 0..3
    const int g    = lane >> 2;          // 0..7
    const int q    = lane & 3;           // 0..3

    const int b  = blockIdx.y;
    const int s0 = blockIdx.x * MT;

    // A fragment LDG bases: rows wm*16+g and +8, f32 col base q*4
    const float* gA0 = patch + ((size_t)b * SS + s0 + wm * 16 + g) * DD + q * 4;
    const float* gA1 = gA0 + 8 * (size_t)DD;

    // B ldmatrix per-lane byte offset (80B rows: 16B-aligned, conflict-free)
    const uint32_t boff = (uint32_t)(((lane & 7) + ((lane >> 4) & 1) * 8) * B8_STRIDE
                                     + ((lane >> 3) & 1) * 16);

    float acc[7][4];
    #pragma unroll
    for (int j = 0; j < 7; ++j) {
        acc[j][0] = 0.f; acc[j][1] = 0.f; acc[j][2] = 0.f; acc[j][3] = 0.f;
    }
    float rsum0 = 0.f, rsum1 = 0.f;

    auto issueB = [&](int kt) {
        uint32_t bdst = sb + OFF_B8 + (kt % NSB) * SZ_BSTG;
        #pragma unroll
        for (int i = 0; i < 2; ++i) {                   // 896 chunks of 16B
            int f = tid + THREADS * i;
            if (f < NP2 * 4) {
                int row = f >> 2, cc = f & 3;
                cp_async16(bdst + row * B8_STRIDE + cc * 16,
                           g_w8 + (size_t)row * DD + kt * KC + cc * 16);
            }
        }
        CP_COMMIT();
    };

    // A staging: st[r2*4 + h*2 + half] (f32), one KC=64 iter ahead
    float4 st[8];
    auto loadA = [&](int kt) {
        #pragma unroll
        for (int h = 0; h < 2; ++h)
            #pragma unroll
            for (int hf = 0; hf < 2; ++hf) {
                int off = kt * KC + h * 32 + hf * 16;
                st[0 * 4 + h * 2 + hf] = *reinterpret_cast<const float4*>(gA0 + off);
                st[1 * 4 + h * 2 + hf] = *reinterpret_cast<const float4*>(gA1 + off);
            }
    };

    issueB(0);
    issueB(1);
    loadA(0);

    for (int kt = 0; kt < NK; ++kt) {
        // ---- pack staged A -> fragment regs + rowsum ----
        uint32_t pa[2][4];
        #pragma unroll
        for (int h = 0; h < 2; ++h) {
            pa[h][0] = pack4_e4m3(st[0 * 4 + h * 2 + 0]);
            pa[h][1] = pack4_e4m3(st[1 * 4 + h * 2 + 0]);
            pa[h][2] = pack4_e4m3(st[0 * 4 + h * 2 + 1]);
            pa[h][3] = pack4_e4m3(st[1 * 4 + h * 2 + 1]);
        }
        #pragma unroll
        for (int i = 0; i < 4; ++i) {
            float4 v0 = st[i], v1 = st[4 + i];
            rsum0 += (v0.x + v0.y) + (v0.z + v0.w);
            rsum1 += (v1.x + v1.y) + (v1.z + v1.w);
        }
        if (kt + 1 < NK) loadA(kt + 1);

        CP_WAIT1();                      // B[kt] arrived (pending <= {B[kt+1]})
        __syncthreads();                 // all warps done with stage (kt-1)%NSB

        if (kt + 2 < NK) issueB(kt + 2); else CP_COMMIT();

        // ---- mma: 2 k32 steps x 7 nfrags; LDSMs batched before MMAs ----
        const uint32_t bstage = sb + OFF_B8 + (kt % NSB) * SZ_BSTG
                              + wn * 56 * B8_STRIDE + boff;
        #pragma unroll
        for (int h = 0; h < 2; ++h) {
            const uint32_t bs = bstage + h * 32;
            uint32_t bf[14];
            LDSM4(bf[0], bf[1], bf[2], bf[3],   bs);
            LDSM4(bf[4], bf[5], bf[6], bf[7],   bs + 16 * B8_STRIDE);
            LDSM4(bf[8], bf[9], bf[10], bf[11], bs + 32 * B8_STRIDE);
            LDSM2(bf[12], bf[13],               bs + 48 * B8_STRIDE);
            #pragma unroll
            for (int j = 0; j < 7; ++j)
                MMA8(acc[j], pa[h][0], pa[h][1], pa[h][2], pa[h][3],
                     bf[2 * j], bf[2 * j + 1]);
        }
    }

    // ---- rowsum: reduce over q; wn==0 warps publish ----
    rsum0 += __shfl_xor_sync(0xffffffffu, rsum0, 1);
    rsum0 += __shfl_xor_sync(0xffffffffu, rsum0, 2);
    rsum1 += __shfl_xor_sync(0xffffffffu, rsum1, 1);
    rsum1 += __shfl_xor_sync(0xffffffffu, rsum1, 2);
    if (wn == 0 && q == 0) {
        rs[wm * 16 + g]     = rsum0;
        rs[wm * 16 + g + 8] = rsum1;
    }
    __syncthreads();

    // ---- epilogue: sigmoid(logit/32 + bias) * rowsum, reduce over s ----
    const float rlo = rs[wm * 16 + g];
    const float rhi = rs[wm * 16 + g + 8];
    #pragma unroll
    for (int j = 0; j < 7; ++j) {
        const int ce = wn * 56 + j * 8 + 2 * q;
        float be = (ce     < CC) ? __ldg(&attn_b[ce])     : 0.f;
        float bo = (ce + 1 < CC) ? __ldg(&attn_b[ce + 1]) : 0.f;
        float pe = sigf(acc[j][0] * WINV + be) * rlo + sigf(acc[j][2] * WINV + be) * rhi;
        float po = sigf(acc[j][1] * WINV + bo) * rlo + sigf(acc[j][3] * WINV + bo) * rhi;
        #pragma unroll
        for (int m = 4; m < 32; m <<= 1) {
            pe += __shfl_xor_sync(0xffffffffu, pe, m);
            po += __shfl_xor_sync(0xffffffffu, po, m);
        }
        if (lane < 4) {                  // lane == q; disjoint slots, no atomics
            wsum[wm * NP2 + ce]     = pe;
            wsum[wm * NP2 + ce + 1] = po;
        }
    }
    __syncthreads();

    if (tid < CC) {
        float s = wsum[0 * NP2 + tid] + wsum[1 * NP2 + tid]
                + wsum[2 * NP2 + tid] + wsum[3 * NP2 + tid];
        float scale = __ldg(&lam[0]) * (1.f / (float)(SS * DD));
        atomicAdd(&out[b * CC + tid], scale * s);
    }
}

// ---------------------------------------------------------------------------
// kernel_launch
// inputs: 0 patch (64,576,768) f32 | 1 class_token (64,768) | 2 attn_w (200,768)
//         3 attn_b (200) | 4 gc_w (200,768) | 5 gc_b (200) | 6 lam (1)
// out: (64,200) f32
// ---------------------------------------------------------------------------
extern "C" void kernel_launch(void* const* d_in, const int* in_sizes, int n_in,
                              void* d_out, int out_size) {
    (void)in_sizes; (void)n_in; (void)out_size;
    const float* patch = (const float*)d_in[0];
    const float* ct    = (const float*)d_in[1];
    const float* aw    = (const float*)d_in[2];
    const float* ab    = (const float*)d_in[3];
    const float* gw    = (const float*)d_in[4];
    const float* gb    = (const float*)d_in[5];
    const float* lam   = (const float*)d_in[6];
    float* out = (float*)d_out;

    cudaFuncSetAttribute(attn_kernel, cudaFuncAttributeMaxDynamicSharedMemorySize,
                         SMEM_TOTAL);

    prep_kernel<<<84 + 1600, 256>>>(aw, ct, gw, gb, out);
    attn_kernel<<<dim3(SS / MT, BB), THREADS, SMEM_TOTAL>>>(patch, ab, lam, out);
}